// round 1
// baseline (speedup 1.0000x reference)
#include <cuda_runtime.h>
#include <cstddef>

// ---------------------------------------------------------------------------
// HMP hierarchical message passing, fp32 baseline.
// Levels: h1[250k,32] h2[500k,32] h3[1M,32] h4[1.5M,32], ring[50k,32].
// up:   hk' = MLP96(concat(hk, h{k-1}[i0], h{k-1}[i1]))        k=2,3,4
// down: h{k-1}' = MLP64(concat(h{k-1}, scatter_add(hk', i0,i1))) k=4,3,2
// ring: hr = segsum(h1'[src] by dst); h1'' = MLP64(concat(h1', scatter(hr[dst] by src)))
// Outputs concatenated: h1'', h2', h3', h4', hr
// ---------------------------------------------------------------------------

#define N1MAX 250000
#define N2MAX 500000
#define N3MAX 1000000

// scratch (device globals: no allocation allowed)
__device__ float g_h2   [(size_t)N2MAX * 32];
__device__ float g_h3   [(size_t)N3MAX * 32];
__device__ float g_acc  [(size_t)N3MAX * 32];
__device__ float g_h1mid[(size_t)N1MAX * 32];

// ---------------------------------------------------------------------------
__global__ void __launch_bounds__(256) zero_kernel(float4* __restrict__ p, int n4)
{
    int i = blockIdx.x * 256 + threadIdx.x;
    if (i < n4) p[i] = make_float4(0.f, 0.f, 0.f, 0.f);
}

// ---------------------------------------------------------------------------
// 96-input MLP: x = [self | prev[i0] | prev[i1]]; out = tanh(x@W1+b1)@W2+b2
__global__ void __launch_bounds__(256) up_mlp_kernel(
    const float* __restrict__ self, const float* __restrict__ prev,
    const int* __restrict__ i0, const int* __restrict__ i1,
    const float* __restrict__ W1, const float* __restrict__ b1,
    const float* __restrict__ W2, const float* __restrict__ b2,
    float* __restrict__ out, int n)
{
    __shared__ float sW1[96 * 32];
    __shared__ float sW2[32 * 32];
    __shared__ float sb[64];
    for (int t = threadIdx.x; t < 96 * 32; t += 256) sW1[t] = W1[t];
    for (int t = threadIdx.x; t < 32 * 32; t += 256) sW2[t] = W2[t];
    if (threadIdx.x < 32)      sb[threadIdx.x] = b1[threadIdx.x];
    else if (threadIdx.x < 64) sb[threadIdx.x] = b2[threadIdx.x - 32];
    __syncthreads();

    int r = blockIdx.x * 256 + threadIdx.x;
    if (r >= n) return;

    const float4* xp0 = (const float4*)(self + (size_t)r * 32);
    const float4* xp1 = (const float4*)(prev + (size_t)i0[r] * 32);
    const float4* xp2 = (const float4*)(prev + (size_t)i1[r] * 32);

    float h[32];
#pragma unroll
    for (int j = 0; j < 32; j++) h[j] = sb[j];

#pragma unroll
    for (int p = 0; p < 3; p++) {
        const float4* xp = (p == 0) ? xp0 : (p == 1) ? xp1 : xp2;
        const float* w = sW1 + p * 1024;
#pragma unroll 1
        for (int k4 = 0; k4 < 8; k4++) {
            float4 v = xp[k4];
            const float* wk = w + k4 * 128;
#pragma unroll
            for (int j = 0; j < 32; j++) {
                float a = h[j];
                a += v.x * wk[j];
                a += v.y * wk[32 + j];
                a += v.z * wk[64 + j];
                a += v.w * wk[96 + j];
                h[j] = a;
            }
        }
    }

#pragma unroll
    for (int j = 0; j < 32; j++) h[j] = tanhf(h[j]);

    float o[32];
#pragma unroll
    for (int j = 0; j < 32; j++) o[j] = sb[32 + j];
#pragma unroll
    for (int k = 0; k < 32; k++) {
        float hk = h[k];
#pragma unroll
        for (int j = 0; j < 32; j++) o[j] += hk * sW2[k * 32 + j];
    }

    float4* op = (float4*)(out + (size_t)r * 32);
#pragma unroll
    for (int q = 0; q < 8; q++)
        op[q] = make_float4(o[q * 4 + 0], o[q * 4 + 1], o[q * 4 + 2], o[q * 4 + 3]);
}

// ---------------------------------------------------------------------------
// 64-input MLP: x = [self | aux] (both row-aligned, no gather)
__global__ void __launch_bounds__(256) down_mlp_kernel(
    const float* __restrict__ self, const float* __restrict__ aux,
    const float* __restrict__ W1, const float* __restrict__ b1,
    const float* __restrict__ W2, const float* __restrict__ b2,
    float* __restrict__ out, int n)
{
    __shared__ float sW1[64 * 32];
    __shared__ float sW2[32 * 32];
    __shared__ float sb[64];
    for (int t = threadIdx.x; t < 64 * 32; t += 256) sW1[t] = W1[t];
    for (int t = threadIdx.x; t < 32 * 32; t += 256) sW2[t] = W2[t];
    if (threadIdx.x < 32)      sb[threadIdx.x] = b1[threadIdx.x];
    else if (threadIdx.x < 64) sb[threadIdx.x] = b2[threadIdx.x - 32];
    __syncthreads();

    int r = blockIdx.x * 256 + threadIdx.x;
    if (r >= n) return;

    const float4* xp0 = (const float4*)(self + (size_t)r * 32);
    const float4* xp1 = (const float4*)(aux  + (size_t)r * 32);

    float h[32];
#pragma unroll
    for (int j = 0; j < 32; j++) h[j] = sb[j];

#pragma unroll
    for (int p = 0; p < 2; p++) {
        const float4* xp = (p == 0) ? xp0 : xp1;
        const float* w = sW1 + p * 1024;
#pragma unroll 1
        for (int k4 = 0; k4 < 8; k4++) {
            float4 v = xp[k4];
            const float* wk = w + k4 * 128;
#pragma unroll
            for (int j = 0; j < 32; j++) {
                float a = h[j];
                a += v.x * wk[j];
                a += v.y * wk[32 + j];
                a += v.z * wk[64 + j];
                a += v.w * wk[96 + j];
                h[j] = a;
            }
        }
    }

#pragma unroll
    for (int j = 0; j < 32; j++) h[j] = tanhf(h[j]);

    float o[32];
#pragma unroll
    for (int j = 0; j < 32; j++) o[j] = sb[32 + j];
#pragma unroll
    for (int k = 0; k < 32; k++) {
        float hk = h[k];
#pragma unroll
        for (int j = 0; j < 32; j++) o[j] += hk * sW2[k * 32 + j];
    }

    float4* op = (float4*)(out + (size_t)r * 32);
#pragma unroll
    for (int q = 0; q < 8; q++)
        op[q] = make_float4(o[q * 4 + 0], o[q * 4 + 1], o[q * 4 + 2], o[q * 4 + 3]);
}

// ---------------------------------------------------------------------------
// acc[i0[r]] += src[r];  acc[i1[r]] += src[r]   (row-wise, 32 floats)
__global__ void __launch_bounds__(256) scatter2_kernel(
    const float* __restrict__ src,
    const int* __restrict__ i0, const int* __restrict__ i1,
    float* __restrict__ acc, int n)
{
    int r = blockIdx.x * 256 + threadIdx.x;
    if (r >= n) return;
    const float4* s = (const float4*)(src + (size_t)r * 32);
    float* d0 = acc + (size_t)i0[r] * 32;
    float* d1 = acc + (size_t)i1[r] * 32;
#pragma unroll
    for (int q = 0; q < 8; q++) {
        float4 v = s[q];
        atomicAdd(d0 + q * 4 + 0, v.x);
        atomicAdd(d0 + q * 4 + 1, v.y);
        atomicAdd(d0 + q * 4 + 2, v.z);
        atomicAdd(d0 + q * 4 + 3, v.w);
        atomicAdd(d1 + q * 4 + 0, v.x);
        atomicAdd(d1 + q * 4 + 1, v.y);
        atomicAdd(d1 + q * 4 + 2, v.z);
        atomicAdd(d1 + q * 4 + 3, v.w);
    }
}

// acc[dstidx[r]] += src[srcidx[r]]
__global__ void __launch_bounds__(256) scatter1_kernel(
    const float* __restrict__ src,
    const int* __restrict__ srcidx, const int* __restrict__ dstidx,
    float* __restrict__ acc, int n)
{
    int r = blockIdx.x * 256 + threadIdx.x;
    if (r >= n) return;
    const float4* s = (const float4*)(src + (size_t)srcidx[r] * 32);
    float* d = acc + (size_t)dstidx[r] * 32;
#pragma unroll
    for (int q = 0; q < 8; q++) {
        float4 v = s[q];
        atomicAdd(d + q * 4 + 0, v.x);
        atomicAdd(d + q * 4 + 1, v.y);
        atomicAdd(d + q * 4 + 2, v.z);
        atomicAdd(d + q * 4 + 3, v.w);
    }
}

// ---------------------------------------------------------------------------
static inline int nblk(int n) { return (n + 255) / 256; }

extern "C" void kernel_launch(void* const* d_in, const int* in_sizes, int n_in,
                              void* d_out, int out_size)
{
    const float* h1     = (const float*)d_in[0];
    const float* h2     = (const float*)d_in[1];
    const float* h3     = (const float*)d_in[2];
    const float* h4     = (const float*)d_in[3];
    const float* upW1   = (const float*)d_in[4];
    const float* upb1   = (const float*)d_in[5];
    const float* upW2   = (const float*)d_in[6];
    const float* upb2   = (const float*)d_in[7];
    const float* dnW1   = (const float*)d_in[8];
    const float* dnb1   = (const float*)d_in[9];
    const float* dnW2   = (const float*)d_in[10];
    const float* dnb2   = (const float*)d_in[11];
    const float* rW1    = (const float*)d_in[12];
    const float* rb1    = (const float*)d_in[13];
    const float* rW2    = (const float*)d_in[14];
    const float* rb2    = (const float*)d_in[15];
    const int* idx2_0   = (const int*)d_in[16];
    const int* idx2_1   = (const int*)d_in[17];
    const int* idx3_0   = (const int*)d_in[18];
    const int* idx3_1   = (const int*)d_in[19];
    const int* idx4_0   = (const int*)d_in[20];
    const int* idx4_1   = (const int*)d_in[21];
    const int* ring_src = (const int*)d_in[22];
    const int* ring_dst = (const int*)d_in[23];

    const int N1 = in_sizes[0] / 32;
    const int N2 = in_sizes[1] / 32;
    const int N3 = in_sizes[2] / 32;
    const int N4 = in_sizes[3] / 32;
    const int ER = in_sizes[22];
    const int NR = out_size / 32 - (N1 + N2 + N3 + N4);

    float* out  = (float*)d_out;
    float* out1 = out;
    float* out2 = out1 + (size_t)N1 * 32;
    float* out3 = out2 + (size_t)N2 * 32;
    float* out4 = out3 + (size_t)N3 * 32;
    float* outR = out4 + (size_t)N4 * 32;

    float *h2buf, *h3buf, *accbuf, *h1mid;
    cudaGetSymbolAddress((void**)&h2buf,  g_h2);
    cudaGetSymbolAddress((void**)&h3buf,  g_h3);
    cudaGetSymbolAddress((void**)&accbuf, g_acc);
    cudaGetSymbolAddress((void**)&h1mid,  g_h1mid);

    // ---- up pass ----
    up_mlp_kernel<<<nblk(N2), 256>>>(h2, h1,    idx2_0, idx2_1,
        upW1 + 0 * 96 * 32, upb1 + 0 * 32, upW2 + 0 * 32 * 32, upb2 + 0 * 32, h2buf, N2);
    up_mlp_kernel<<<nblk(N3), 256>>>(h3, h2buf, idx3_0, idx3_1,
        upW1 + 1 * 96 * 32, upb1 + 1 * 32, upW2 + 1 * 32 * 32, upb2 + 1 * 32, h3buf, N3);
    up_mlp_kernel<<<nblk(N4), 256>>>(h4, h3buf, idx4_0, idx4_1,
        upW1 + 2 * 96 * 32, upb1 + 2 * 32, upW2 + 2 * 32 * 32, upb2 + 2 * 32, out4, N4);

    // ---- down pass: k=4 -> level 3 ----
    zero_kernel<<<nblk(N3 * 8), 256>>>((float4*)accbuf, N3 * 8);
    scatter2_kernel<<<nblk(N4), 256>>>(out4, idx4_0, idx4_1, accbuf, N4);
    down_mlp_kernel<<<nblk(N3), 256>>>(h3buf, accbuf,
        dnW1 + 2 * 64 * 32, dnb1 + 2 * 32, dnW2 + 2 * 32 * 32, dnb2 + 2 * 32, out3, N3);

    // ---- down pass: k=3 -> level 2 ----
    zero_kernel<<<nblk(N2 * 8), 256>>>((float4*)accbuf, N2 * 8);
    scatter2_kernel<<<nblk(N3), 256>>>(out3, idx3_0, idx3_1, accbuf, N3);
    down_mlp_kernel<<<nblk(N2), 256>>>(h2buf, accbuf,
        dnW1 + 1 * 64 * 32, dnb1 + 1 * 32, dnW2 + 1 * 32 * 32, dnb2 + 1 * 32, out2, N2);

    // ---- down pass: k=2 -> level 1 ----
    zero_kernel<<<nblk(N1 * 8), 256>>>((float4*)accbuf, N1 * 8);
    scatter2_kernel<<<nblk(N2), 256>>>(out2, idx2_0, idx2_1, accbuf, N2);
    down_mlp_kernel<<<nblk(N1), 256>>>(h1, accbuf,
        dnW1 + 0 * 64 * 32, dnb1 + 0 * 32, dnW2 + 0 * 32 * 32, dnb2 + 0 * 32, h1mid, N1);

    // ---- ring ----
    zero_kernel<<<nblk(NR * 8), 256>>>((float4*)outR, NR * 8);
    scatter1_kernel<<<nblk(ER), 256>>>(h1mid, ring_src, ring_dst, outR, ER);   // h_ring
    zero_kernel<<<nblk(N1 * 8), 256>>>((float4*)accbuf, N1 * 8);
    scatter1_kernel<<<nblk(ER), 256>>>(outR, ring_dst, ring_src, accbuf, ER);  // h_ring_down
    down_mlp_kernel<<<nblk(N1), 256>>>(h1mid, accbuf,
        rW1, rb1, rW2, rb2, out1, N1);
}

// round 2
// speedup vs baseline: 1.1853x; 1.1853x over previous
#include <cuda_runtime.h>
#include <cstddef>

// ---------------------------------------------------------------------------
// HMP hierarchical message passing — R2: f32x2 packed-FMA MLPs (2 rows/thread),
// vector float4 atomics for scatter, fast tanh.
// ---------------------------------------------------------------------------

typedef unsigned long long ull;

#define N1MAX 250000
#define N2MAX 500000
#define N3MAX 1000000

// scratch (device globals: no allocation allowed)
__device__ float g_h2   [(size_t)N2MAX * 32];
__device__ float g_h3   [(size_t)N3MAX * 32];
__device__ float g_acc  [(size_t)N3MAX * 32];
__device__ float g_h1mid[(size_t)N1MAX * 32];

// ---------------------------------------------------------------------------
__device__ __forceinline__ ull pack2(float lo, float hi)
{
    ull p;
    asm("mov.b64 %0, {%1, %2};" : "=l"(p) : "f"(lo), "f"(hi));
    return p;
}
__device__ __forceinline__ void unpack2(ull p, float& lo, float& hi)
{
    asm("mov.b64 {%0, %1}, %2;" : "=f"(lo), "=f"(hi) : "l"(p));
}
// packed dual fp32 FMA (sm_100+): d = a*b + c on both halves
__device__ __forceinline__ ull ffma2(ull a, ull b, ull c)
{
    ull d;
    asm("fma.rn.f32x2 %0, %1, %2, %3;" : "=l"(d) : "l"(a), "l"(b), "l"(c));
    return d;
}

__device__ __forceinline__ float tanh_fast(float x)
{
    float cx = fminf(fmaxf(x, -15.f), 15.f);
    float e  = __expf(2.f * cx);
    return __fdividef(e - 1.f, e + 1.f);
}

// ---------------------------------------------------------------------------
__global__ void __launch_bounds__(256) zero_kernel(float4* __restrict__ p, int n4)
{
    int i = blockIdx.x * 256 + threadIdx.x;
    if (i < n4) p[i] = make_float4(0.f, 0.f, 0.f, 0.f);
}

// ---------------------------------------------------------------------------
// up MLP (K=96): x = [self | prev[i0] | prev[i1]]; out = tanh(x@W1+b1)@W2+b2
// 2 rows per thread via f32x2.
__global__ void __launch_bounds__(128) up_mlp2_kernel(
    const float* __restrict__ self, const float* __restrict__ prev,
    const int* __restrict__ i0, const int* __restrict__ i1,
    const float* __restrict__ W1, const float* __restrict__ b1,
    const float* __restrict__ W2, const float* __restrict__ b2,
    float* __restrict__ out, int n)
{
    __shared__ __align__(16) ull sW1[96 * 32];   // duplicated (w,w) pairs
    __shared__ __align__(16) ull sW2[32 * 32];
    __shared__ ull sB1[32], sB2[32];
    for (int t = threadIdx.x; t < 96 * 32; t += 128) { float w = W1[t]; sW1[t] = pack2(w, w); }
    for (int t = threadIdx.x; t < 32 * 32; t += 128) { float w = W2[t]; sW2[t] = pack2(w, w); }
    if (threadIdx.x < 32) {
        float v = b1[threadIdx.x]; sB1[threadIdx.x] = pack2(v, v);
        float u = b2[threadIdx.x]; sB2[threadIdx.x] = pack2(u, u);
    }
    __syncthreads();

    int t  = blockIdx.x * 128 + threadIdx.x;
    int r0 = 2 * t;
    if (r0 >= n) return;
    int r1 = min(r0 + 1, n - 1);

    const float4* a0[3] = {
        (const float4*)(self + (size_t)r0 * 32),
        (const float4*)(prev + (size_t)i0[r0] * 32),
        (const float4*)(prev + (size_t)i1[r0] * 32)};
    const float4* a1[3] = {
        (const float4*)(self + (size_t)r1 * 32),
        (const float4*)(prev + (size_t)i0[r1] * 32),
        (const float4*)(prev + (size_t)i1[r1] * 32)};

    ull acc[32];
#pragma unroll
    for (int j = 0; j < 32; j++) acc[j] = sB1[j];

#pragma unroll
    for (int p = 0; p < 3; p++) {
#pragma unroll 2
        for (int k4 = 0; k4 < 8; k4++) {
            float4 v0 = a0[p][k4];
            float4 v1 = a1[p][k4];
            ull xp[4];
            xp[0] = pack2(v0.x, v1.x); xp[1] = pack2(v0.y, v1.y);
            xp[2] = pack2(v0.z, v1.z); xp[3] = pack2(v0.w, v1.w);
#pragma unroll
            for (int kk = 0; kk < 4; kk++) {
                const ulonglong2* wrow =
                    (const ulonglong2*)(sW1 + ((p * 8 + k4) * 4 + kk) * 32);
#pragma unroll
                for (int j2 = 0; j2 < 16; j2++) {
                    ulonglong2 w = wrow[j2];
                    acc[2 * j2]     = ffma2(xp[kk], w.x, acc[2 * j2]);
                    acc[2 * j2 + 1] = ffma2(xp[kk], w.y, acc[2 * j2 + 1]);
                }
            }
        }
    }

#pragma unroll
    for (int j = 0; j < 32; j++) {
        float u, v; unpack2(acc[j], u, v);
        acc[j] = pack2(tanh_fast(u), tanh_fast(v));
    }

    ull o[32];
#pragma unroll
    for (int j = 0; j < 32; j++) o[j] = sB2[j];
#pragma unroll
    for (int k = 0; k < 32; k++) {
        const ulonglong2* wrow = (const ulonglong2*)(sW2 + k * 32);
        ull hk = acc[k];
#pragma unroll
        for (int j2 = 0; j2 < 16; j2++) {
            ulonglong2 w = wrow[j2];
            o[2 * j2]     = ffma2(hk, w.x, o[2 * j2]);
            o[2 * j2 + 1] = ffma2(hk, w.y, o[2 * j2 + 1]);
        }
    }

    float4* o0 = (float4*)(out + (size_t)r0 * 32);
    float4* o1 = (float4*)(out + (size_t)r1 * 32);
#pragma unroll
    for (int q = 0; q < 8; q++) {
        float a, b, c, d, e, f, g, h;
        unpack2(o[4 * q + 0], a, e); unpack2(o[4 * q + 1], b, f);
        unpack2(o[4 * q + 2], c, g); unpack2(o[4 * q + 3], d, h);
        o0[q] = make_float4(a, b, c, d);
        if (r1 != r0) o1[q] = make_float4(e, f, g, h);
    }
}

// ---------------------------------------------------------------------------
// down/ring MLP (K=64): x = [self | aux] (row-aligned)
__global__ void __launch_bounds__(128) down_mlp2_kernel(
    const float* __restrict__ self, const float* __restrict__ aux,
    const float* __restrict__ W1, const float* __restrict__ b1,
    const float* __restrict__ W2, const float* __restrict__ b2,
    float* __restrict__ out, int n)
{
    __shared__ __align__(16) ull sW1[64 * 32];
    __shared__ __align__(16) ull sW2[32 * 32];
    __shared__ ull sB1[32], sB2[32];
    for (int t = threadIdx.x; t < 64 * 32; t += 128) { float w = W1[t]; sW1[t] = pack2(w, w); }
    for (int t = threadIdx.x; t < 32 * 32; t += 128) { float w = W2[t]; sW2[t] = pack2(w, w); }
    if (threadIdx.x < 32) {
        float v = b1[threadIdx.x]; sB1[threadIdx.x] = pack2(v, v);
        float u = b2[threadIdx.x]; sB2[threadIdx.x] = pack2(u, u);
    }
    __syncthreads();

    int t  = blockIdx.x * 128 + threadIdx.x;
    int r0 = 2 * t;
    if (r0 >= n) return;
    int r1 = min(r0 + 1, n - 1);

    const float4* a0[2] = {
        (const float4*)(self + (size_t)r0 * 32),
        (const float4*)(aux  + (size_t)r0 * 32)};
    const float4* a1[2] = {
        (const float4*)(self + (size_t)r1 * 32),
        (const float4*)(aux  + (size_t)r1 * 32)};

    ull acc[32];
#pragma unroll
    for (int j = 0; j < 32; j++) acc[j] = sB1[j];

#pragma unroll
    for (int p = 0; p < 2; p++) {
#pragma unroll 2
        for (int k4 = 0; k4 < 8; k4++) {
            float4 v0 = a0[p][k4];
            float4 v1 = a1[p][k4];
            ull xp[4];
            xp[0] = pack2(v0.x, v1.x); xp[1] = pack2(v0.y, v1.y);
            xp[2] = pack2(v0.z, v1.z); xp[3] = pack2(v0.w, v1.w);
#pragma unroll
            for (int kk = 0; kk < 4; kk++) {
                const ulonglong2* wrow =
                    (const ulonglong2*)(sW1 + ((p * 8 + k4) * 4 + kk) * 32);
#pragma unroll
                for (int j2 = 0; j2 < 16; j2++) {
                    ulonglong2 w = wrow[j2];
                    acc[2 * j2]     = ffma2(xp[kk], w.x, acc[2 * j2]);
                    acc[2 * j2 + 1] = ffma2(xp[kk], w.y, acc[2 * j2 + 1]);
                }
            }
        }
    }

#pragma unroll
    for (int j = 0; j < 32; j++) {
        float u, v; unpack2(acc[j], u, v);
        acc[j] = pack2(tanh_fast(u), tanh_fast(v));
    }

    ull o[32];
#pragma unroll
    for (int j = 0; j < 32; j++) o[j] = sB2[j];
#pragma unroll
    for (int k = 0; k < 32; k++) {
        const ulonglong2* wrow = (const ulonglong2*)(sW2 + k * 32);
        ull hk = acc[k];
#pragma unroll
        for (int j2 = 0; j2 < 16; j2++) {
            ulonglong2 w = wrow[j2];
            o[2 * j2]     = ffma2(hk, w.x, o[2 * j2]);
            o[2 * j2 + 1] = ffma2(hk, w.y, o[2 * j2 + 1]);
        }
    }

    float4* o0 = (float4*)(out + (size_t)r0 * 32);
    float4* o1 = (float4*)(out + (size_t)r1 * 32);
#pragma unroll
    for (int q = 0; q < 8; q++) {
        float a, b, c, d, e, f, g, h;
        unpack2(o[4 * q + 0], a, e); unpack2(o[4 * q + 1], b, f);
        unpack2(o[4 * q + 2], c, g); unpack2(o[4 * q + 3], d, h);
        o0[q] = make_float4(a, b, c, d);
        if (r1 != r0) o1[q] = make_float4(e, f, g, h);
    }
}

// ---------------------------------------------------------------------------
// acc[i0[r]] += src[r]; acc[i1[r]] += src[r]   (row-wise, vector atomics)
__global__ void __launch_bounds__(256) scatter2_kernel(
    const float* __restrict__ src,
    const int* __restrict__ i0, const int* __restrict__ i1,
    float* __restrict__ acc, int n)
{
    int r = blockIdx.x * 256 + threadIdx.x;
    if (r >= n) return;
    const float4* s = (const float4*)(src + (size_t)r * 32);
    float4* d0 = (float4*)(acc + (size_t)i0[r] * 32);
    float4* d1 = (float4*)(acc + (size_t)i1[r] * 32);
#pragma unroll
    for (int q = 0; q < 8; q++) {
        float4 v = s[q];
        atomicAdd(d0 + q, v);
        atomicAdd(d1 + q, v);
    }
}

// acc[dstidx[r]] += src[srcidx[r]]
__global__ void __launch_bounds__(256) scatter1_kernel(
    const float* __restrict__ src,
    const int* __restrict__ srcidx, const int* __restrict__ dstidx,
    float* __restrict__ acc, int n)
{
    int r = blockIdx.x * 256 + threadIdx.x;
    if (r >= n) return;
    const float4* s = (const float4*)(src + (size_t)srcidx[r] * 32);
    float4* d = (float4*)(acc + (size_t)dstidx[r] * 32);
#pragma unroll
    for (int q = 0; q < 8; q++) {
        float4 v = s[q];
        atomicAdd(d + q, v);
    }
}

// ---------------------------------------------------------------------------
static inline int nblk256(int n) { return (n + 255) / 256; }
static inline int nblk2(int n)   { return (n + 255) / 256; }  // 128 thr × 2 rows

extern "C" void kernel_launch(void* const* d_in, const int* in_sizes, int n_in,
                              void* d_out, int out_size)
{
    const float* h1     = (const float*)d_in[0];
    const float* h2     = (const float*)d_in[1];
    const float* h3     = (const float*)d_in[2];
    const float* h4     = (const float*)d_in[3];
    const float* upW1   = (const float*)d_in[4];
    const float* upb1   = (const float*)d_in[5];
    const float* upW2   = (const float*)d_in[6];
    const float* upb2   = (const float*)d_in[7];
    const float* dnW1   = (const float*)d_in[8];
    const float* dnb1   = (const float*)d_in[9];
    const float* dnW2   = (const float*)d_in[10];
    const float* dnb2   = (const float*)d_in[11];
    const float* rW1    = (const float*)d_in[12];
    const float* rb1    = (const float*)d_in[13];
    const float* rW2    = (const float*)d_in[14];
    const float* rb2    = (const float*)d_in[15];
    const int* idx2_0   = (const int*)d_in[16];
    const int* idx2_1   = (const int*)d_in[17];
    const int* idx3_0   = (const int*)d_in[18];
    const int* idx3_1   = (const int*)d_in[19];
    const int* idx4_0   = (const int*)d_in[20];
    const int* idx4_1   = (const int*)d_in[21];
    const int* ring_src = (const int*)d_in[22];
    const int* ring_dst = (const int*)d_in[23];

    const int N1 = in_sizes[0] / 32;
    const int N2 = in_sizes[1] / 32;
    const int N3 = in_sizes[2] / 32;
    const int N4 = in_sizes[3] / 32;
    const int ER = in_sizes[22];
    const int NR = out_size / 32 - (N1 + N2 + N3 + N4);

    float* out  = (float*)d_out;
    float* out1 = out;
    float* out2 = out1 + (size_t)N1 * 32;
    float* out3 = out2 + (size_t)N2 * 32;
    float* out4 = out3 + (size_t)N3 * 32;
    float* outR = out4 + (size_t)N4 * 32;

    float *h2buf, *h3buf, *accbuf, *h1mid;
    cudaGetSymbolAddress((void**)&h2buf,  g_h2);
    cudaGetSymbolAddress((void**)&h3buf,  g_h3);
    cudaGetSymbolAddress((void**)&accbuf, g_acc);
    cudaGetSymbolAddress((void**)&h1mid,  g_h1mid);

    // ---- up pass ----
    up_mlp2_kernel<<<nblk2(N2), 128>>>(h2, h1,    idx2_0, idx2_1,
        upW1 + 0 * 96 * 32, upb1 + 0 * 32, upW2 + 0 * 32 * 32, upb2 + 0 * 32, h2buf, N2);
    up_mlp2_kernel<<<nblk2(N3), 128>>>(h3, h2buf, idx3_0, idx3_1,
        upW1 + 1 * 96 * 32, upb1 + 1 * 32, upW2 + 1 * 32 * 32, upb2 + 1 * 32, h3buf, N3);
    up_mlp2_kernel<<<nblk2(N4), 128>>>(h4, h3buf, idx4_0, idx4_1,
        upW1 + 2 * 96 * 32, upb1 + 2 * 32, upW2 + 2 * 32 * 32, upb2 + 2 * 32, out4, N4);

    // ---- down pass: k=4 -> level 3 ----
    zero_kernel<<<nblk256(N3 * 8), 256>>>((float4*)accbuf, N3 * 8);
    scatter2_kernel<<<nblk256(N4), 256>>>(out4, idx4_0, idx4_1, accbuf, N4);
    down_mlp2_kernel<<<nblk2(N3), 128>>>(h3buf, accbuf,
        dnW1 + 2 * 64 * 32, dnb1 + 2 * 32, dnW2 + 2 * 32 * 32, dnb2 + 2 * 32, out3, N3);

    // ---- down pass: k=3 -> level 2 ----
    zero_kernel<<<nblk256(N2 * 8), 256>>>((float4*)accbuf, N2 * 8);
    scatter2_kernel<<<nblk256(N3), 256>>>(out3, idx3_0, idx3_1, accbuf, N3);
    down_mlp2_kernel<<<nblk2(N2), 128>>>(h2buf, accbuf,
        dnW1 + 1 * 64 * 32, dnb1 + 1 * 32, dnW2 + 1 * 32 * 32, dnb2 + 1 * 32, out2, N2);

    // ---- down pass: k=2 -> level 1 ----
    zero_kernel<<<nblk256(N1 * 8), 256>>>((float4*)accbuf, N1 * 8);
    scatter2_kernel<<<nblk256(N2), 256>>>(out2, idx2_0, idx2_1, accbuf, N2);
    down_mlp2_kernel<<<nblk2(N1), 128>>>(h1, accbuf,
        dnW1 + 0 * 64 * 32, dnb1 + 0 * 32, dnW2 + 0 * 32 * 32, dnb2 + 0 * 32, h1mid, N1);

    // ---- ring ----
    zero_kernel<<<nblk256(NR * 8), 256>>>((float4*)outR, NR * 8);
    scatter1_kernel<<<nblk256(ER), 256>>>(h1mid, ring_src, ring_dst, outR, ER);   // h_ring
    zero_kernel<<<nblk256(N1 * 8), 256>>>((float4*)accbuf, N1 * 8);
    scatter1_kernel<<<nblk256(ER), 256>>>(outR, ring_dst, ring_src, accbuf, ER);  // h_ring_down
    down_mlp2_kernel<<<nblk2(N1), 128>>>(h1mid, accbuf,
        rW1, rb1, rW2, rb2, out1, N1);
}